// round 3
// baseline (speedup 1.0000x reference)
#include <cuda_runtime.h>

#define NN   100000
#define NE   1600000
#define NG   64
#define DIN  128
#define HID  256
#define NB1  391          // ceil(NN/256)
#define SPLITK 74
#define CHUNK  1352       // 74*1352 >= NN
#define PBLK   296
#define PCH    338        // 296*338 >= NN

// ------------- static device scratch (no allocations allowed) -------------
__device__ __align__(16) float g_agg1[(size_t)NN * DIN];   // 51.2 MB
__device__ __align__(16) float g_h1[(size_t)NN * HID];     // 102.4 MB
__device__ __align__(16) float g_coef[(size_t)NN * NG];    // 25.6 MB
__device__ __align__(16) float g_Qa[NG * HID];
__device__ __align__(16) float g_P[NG * HID];
__device__ int   g_cnt[NN];
__device__ int   g_eoff[NN];
__device__ int   g_wpos[NN];
__device__ int   g_bsum[NB1];
__device__ int   g_boff[512];
__device__ int   g_ncnt[NG];
__device__ float g_invcnt[NN];
__device__ float g_invng[NG];
__device__ int   g_esrc[NE];

// --------------------------- zero scratch ---------------------------
__global__ void zero_all() {
    size_t i = (size_t)blockIdx.x * blockDim.x + threadIdx.x;
    size_t stride = (size_t)gridDim.x * blockDim.x;
    float4 z = make_float4(0.f, 0.f, 0.f, 0.f);
    for (size_t j = i; j < (size_t)NN * NG / 4; j += stride)
        ((float4*)g_coef)[j] = z;
    for (size_t j = i; j < NN; j += stride) g_cnt[j] = 0;
    for (size_t j = i; j < NG * HID; j += stride) { g_Qa[j] = 0.f; g_P[j] = 0.f; }
    if (i < NG) g_ncnt[i] = 0;
}

// --------------------------- degree count ---------------------------
__global__ void count_k(const int* __restrict__ ei) {
    int e = blockIdx.x * blockDim.x + threadIdx.x;
    if (e < NE) {
        int d = ei[NE + e];
        if ((unsigned)d < NN) atomicAdd(&g_cnt[d], 1);
    }
}

// --------------------------- per-graph node count ---------------------------
__global__ void gcount_k(const int* __restrict__ batch) {
    int i = blockIdx.x * blockDim.x + threadIdx.x;
    if (i < NN) {
        int g = batch[i];
        if ((unsigned)g < NG) atomicAdd(&g_ncnt[g], 1);
    }
}

// --------------------------- exclusive scan of degrees ---------------------------
__global__ void scan1_k() {
    __shared__ int sh[256];
    int t = threadIdx.x;
    int i = blockIdx.x * 256 + t;
    int val = (i < NN) ? g_cnt[i] : 0;
    sh[t] = val;
    __syncthreads();
    for (int d = 1; d < 256; d <<= 1) {
        int add = (t >= d) ? sh[t - d] : 0;
        __syncthreads();
        sh[t] += add;
        __syncthreads();
    }
    if (i < NN) g_eoff[i] = sh[t] - val;
    if (t == 255) g_bsum[blockIdx.x] = sh[255];
}

__global__ void scan2_k() {
    __shared__ int sh[512];
    int t = threadIdx.x;
    int val = (t < NB1) ? g_bsum[t] : 0;
    sh[t] = val;
    __syncthreads();
    for (int d = 1; d < 512; d <<= 1) {
        int add = (t >= d) ? sh[t - d] : 0;
        __syncthreads();
        sh[t] += add;
        __syncthreads();
    }
    g_boff[t] = sh[t] - val;
}

__global__ void scan3_k() {
    int i = blockIdx.x * blockDim.x + threadIdx.x;
    if (i < NN) {
        int off = g_eoff[i] + g_boff[i >> 8];
        g_eoff[i] = off;
        g_wpos[i] = off;
        g_invcnt[i] = 1.0f / fmaxf((float)g_cnt[i], 1.0f);
    }
    if (i < NG) g_invng[i] = 1.0f / fmaxf((float)g_ncnt[i], 1.0f);
}

// --------------------------- counting-sort placement (CSR by dst) ---------------------------
__global__ void place_k(const int* __restrict__ ei) {
    int e = blockIdx.x * blockDim.x + threadIdx.x;
    if (e < NE) {
        int s = ei[e];
        int d = ei[NE + e];
        if ((unsigned)s < NN && (unsigned)d < NN) {
            int p = atomicAdd(&g_wpos[d], 1);
            g_esrc[p] = s;
        }
    }
}

// --------------------------- layer-1 mean aggregation (warp per node) ---------------------------
__global__ void agg1_k(const float* __restrict__ x) {
    int gtid = blockIdx.x * blockDim.x + threadIdx.x;
    int v = gtid >> 5;
    if (v >= NN) return;
    int lane = gtid & 31;
    int start = g_eoff[v];
    int end = (v + 1 < NN) ? g_eoff[v + 1] : NE;
    float4 acc = make_float4(0.f, 0.f, 0.f, 0.f);
    for (int i = start; i < end; ++i) {
        int s = g_esrc[i];
        float4 t = *(const float4*)&x[(size_t)s * DIN + lane * 4];
        acc.x += t.x; acc.y += t.y; acc.z += t.z; acc.w += t.w;
    }
    float w = g_invcnt[v];
    acc.x *= w; acc.y *= w; acc.z *= w; acc.w *= w;
    *(float4*)&g_agg1[(size_t)v * DIN + lane * 4] = acc;
}

// --------------------------- coef build (scalar edge pass) ---------------------------
__global__ void coef_k(const int* __restrict__ ei,
                       const int* __restrict__ batch) {
    int e = blockIdx.x * blockDim.x + threadIdx.x;
    if (e < NE) {
        int s = ei[e];
        int d = ei[NE + e];
        if ((unsigned)s < NN && (unsigned)d < NN) {
            int g = batch[d];
            atomicAdd(&g_coef[(size_t)s * NG + g], g_invcnt[d]);
        }
    }
}

// --------------------------- GEMM1: h1 = relu([x|agg1]@[W1r;W1l] + b1) ---------------------------
__global__ void __launch_bounds__(256) gemm1_k(
    const float* __restrict__ x, const float* __restrict__ W1l,
    const float* __restrict__ b1, const float* __restrict__ W1r) {
    __shared__ float As[8][128];
    __shared__ float Bs[8][128];
    int tid = threadIdx.x;
    int tx = tid & 15, ty = tid >> 4;
    int m0 = blockIdx.y * 128;
    int col0 = blockIdx.x * 128;
    float acc[8][8];
#pragma unroll
    for (int i = 0; i < 8; i++)
#pragma unroll
        for (int j = 0; j < 8; j++) acc[i][j] = 0.f;

    int arow = tid >> 1;
    int ak4 = (tid & 1) * 4;
    int brow = tid >> 5;
    int bc4 = (tid & 31) * 4;
    int gr = m0 + arow;

    for (int kc = 0; kc < 2 * DIN; kc += 8) {
        const float* Ap = (kc < DIN) ? x : g_agg1;
        const float* Bp = (kc < DIN) ? W1r : W1l;
        int koff = kc & (DIN - 1);
        float4 av = make_float4(0.f, 0.f, 0.f, 0.f);
        if (gr < NN) av = *(const float4*)&Ap[(size_t)gr * DIN + koff + ak4];
        float4 bv = *(const float4*)&Bp[(size_t)(koff + brow) * HID + col0 + bc4];
        __syncthreads();
        As[ak4 + 0][arow] = av.x;
        As[ak4 + 1][arow] = av.y;
        As[ak4 + 2][arow] = av.z;
        As[ak4 + 3][arow] = av.w;
        *(float4*)&Bs[brow][bc4] = bv;
        __syncthreads();
#pragma unroll
        for (int k = 0; k < 8; k++) {
            float a[8], b[8];
            *(float4*)&a[0] = *(float4*)&As[k][ty * 8];
            *(float4*)&a[4] = *(float4*)&As[k][ty * 8 + 4];
            *(float4*)&b[0] = *(float4*)&Bs[k][tx * 8];
            *(float4*)&b[4] = *(float4*)&Bs[k][tx * 8 + 4];
#pragma unroll
            for (int i = 0; i < 8; i++)
#pragma unroll
                for (int j = 0; j < 8; j++) acc[i][j] += a[i] * b[j];
        }
    }

    float bias[8];
    *(float4*)&bias[0] = *(const float4*)&b1[col0 + tx * 8];
    *(float4*)&bias[4] = *(const float4*)&b1[col0 + tx * 8 + 4];
#pragma unroll
    for (int i = 0; i < 8; i++) {
        int r = m0 + ty * 8 + i;
        if (r < NN) {
            float4 o0, o1;
            o0.x = fmaxf(acc[i][0] + bias[0], 0.f);
            o0.y = fmaxf(acc[i][1] + bias[1], 0.f);
            o0.z = fmaxf(acc[i][2] + bias[2], 0.f);
            o0.w = fmaxf(acc[i][3] + bias[3], 0.f);
            o1.x = fmaxf(acc[i][4] + bias[4], 0.f);
            o1.y = fmaxf(acc[i][5] + bias[5], 0.f);
            o1.z = fmaxf(acc[i][6] + bias[6], 0.f);
            o1.w = fmaxf(acc[i][7] + bias[7], 0.f);
            *(float4*)&g_h1[(size_t)r * HID + col0 + tx * 8] = o0;
            *(float4*)&g_h1[(size_t)r * HID + col0 + tx * 8 + 4] = o1;
        }
    }
}

// --------------------------- GEMM2: Qa = coef^T @ h1 (split-K) ---------------------------
__global__ void __launch_bounds__(128) gemm2_k() {
    __shared__ float As[16][64];
    __shared__ float Bs[16][128];
    int tid = threadIdx.x;
    int dx = tid & 15, gy = tid >> 4;
    int d0 = blockIdx.x * 128;
    int n0 = blockIdx.y * CHUNK;
    int n1 = n0 + CHUNK;
    if (n1 > NN) n1 = NN;
    float acc[8][8];
#pragma unroll
    for (int i = 0; i < 8; i++)
#pragma unroll
        for (int j = 0; j < 8; j++) acc[i][j] = 0.f;

    int anode = tid >> 3;            // 0..15
    int ag = (tid & 7) * 8;          // 0..56
    int bnode = tid >> 5;            // 0..3
    int bc = (tid & 31) * 4;

    for (int kk = n0; kk < n1; kk += 16) {
        float4 a0 = make_float4(0.f, 0.f, 0.f, 0.f), a1 = a0;
        int an = kk + anode;
        if (an < n1) {
            a0 = *(const float4*)&g_coef[(size_t)an * NG + ag];
            a1 = *(const float4*)&g_coef[(size_t)an * NG + ag + 4];
        }
        float4 bv[4];
#pragma unroll
        for (int q = 0; q < 4; q++) {
            int bn = kk + q * 4 + bnode;
            bv[q] = make_float4(0.f, 0.f, 0.f, 0.f);
            if (bn < n1) bv[q] = *(const float4*)&g_h1[(size_t)bn * HID + d0 + bc];
        }
        __syncthreads();
        *(float4*)&As[anode][ag] = a0;
        *(float4*)&As[anode][ag + 4] = a1;
#pragma unroll
        for (int q = 0; q < 4; q++)
            *(float4*)&Bs[q * 4 + bnode][bc] = bv[q];
        __syncthreads();
#pragma unroll
        for (int k = 0; k < 16; k++) {
            float a[8], b[8];
            *(float4*)&a[0] = *(float4*)&As[k][gy * 8];
            *(float4*)&a[4] = *(float4*)&As[k][gy * 8 + 4];
            *(float4*)&b[0] = *(float4*)&Bs[k][dx * 8];
            *(float4*)&b[4] = *(float4*)&Bs[k][dx * 8 + 4];
#pragma unroll
            for (int i = 0; i < 8; i++)
#pragma unroll
                for (int j = 0; j < 8; j++) acc[i][j] += a[i] * b[j];
        }
    }
#pragma unroll
    for (int i = 0; i < 8; i++)
#pragma unroll
        for (int j = 0; j < 8; j++)
            atomicAdd(&g_Qa[(gy * 8 + i) * HID + d0 + dx * 8 + j], acc[i][j]);
}

// --------------------------- P: segmented sum of h1 over sorted batch ---------------------------
__global__ void ppool_k(const int* __restrict__ batch) {
    int n0 = blockIdx.x * PCH;
    if (n0 >= NN) return;
    int n1 = n0 + PCH;
    if (n1 > NN) n1 = NN;
    int d = threadIdx.x;
    float ps = 0.f;
    int curg = batch[n0];
    for (int v = n0; v < n1; v++) {
        int g = batch[v];
        if (g != curg) {
            atomicAdd(&g_P[curg * HID + d], ps);
            ps = 0.f;
            curg = g;
        }
        ps += g_h1[(size_t)v * HID + d];
    }
    atomicAdd(&g_P[curg * HID + d], ps);
}

// --------------------------- final: layer2 fold + pool + MLP head ---------------------------
__global__ void final_k(const float* __restrict__ gattr,
                        const float* __restrict__ W2l, const float* __restrict__ b2,
                        const float* __restrict__ W2r,
                        const float* __restrict__ Wf1, const float* __restrict__ bf1,
                        const float* __restrict__ Wf2, const float* __restrict__ bf2,
                        float* __restrict__ out) {
    __shared__ float q[HID], p[HID], pooled[HID], red[HID];
    int g = blockIdx.x, j = threadIdx.x;
    q[j] = g_Qa[g * HID + j];
    p[j] = g_P[g * HID + j];
    __syncthreads();
    float acc = 0.f;
    for (int k = 0; k < HID; k++)
        acc += q[k] * W2l[k * HID + j] + p[k] * W2r[k * HID + j];
    pooled[j] = g_invng[g] * acc + b2[j];
    __syncthreads();
    float a2 = bf1[j];
    for (int k = 0; k < HID; k++)
        a2 += pooled[k] * Wf1[k * HID + j];
    for (int a = 0; a < 8; a++)
        a2 += gattr[g * 8 + a] * Wf1[(HID + a) * HID + j];
    float t1 = fmaxf(a2, 0.f);
    red[j] = t1 * Wf2[j];
    __syncthreads();
    for (int s = 128; s > 0; s >>= 1) {
        if (j < s) red[j] += red[j + s];
        __syncthreads();
    }
    if (j == 0) out[g] = red[0] + bf2[0];
}

// --------------------------- launch ---------------------------
extern "C" void kernel_launch(void* const* d_in, const int* in_sizes, int n_in,
                              void* d_out, int out_size) {
    const float* x = (const float*)d_in[0];
    const int* ei = (const int*)d_in[1];
    const int* batch = (const int*)d_in[2];
    const float* gattr = (const float*)d_in[3];
    const float* W1l = (const float*)d_in[4];
    const float* b1  = (const float*)d_in[5];
    const float* W1r = (const float*)d_in[6];
    const float* W2l = (const float*)d_in[7];
    const float* b2  = (const float*)d_in[8];
    const float* W2r = (const float*)d_in[9];
    const float* Wf1 = (const float*)d_in[10];
    const float* bf1 = (const float*)d_in[11];
    const float* Wf2 = (const float*)d_in[12];
    const float* bf2 = (const float*)d_in[13];
    float* out = (float*)d_out;

    zero_all<<<2048, 256>>>();
    count_k<<<(NE + 255) / 256, 256>>>(ei);
    gcount_k<<<(NN + 255) / 256, 256>>>(batch);
    scan1_k<<<NB1, 256>>>();
    scan2_k<<<1, 512>>>();
    scan3_k<<<NB1, 256>>>();
    place_k<<<(NE + 255) / 256, 256>>>(ei);
    agg1_k<<<(NN * 32 + 255) / 256, 256>>>(x);
    coef_k<<<(NE + 255) / 256, 256>>>(ei, batch);
    gemm1_k<<<dim3(2, (NN + 127) / 128), 256>>>(x, W1l, b1, W1r);
    gemm2_k<<<dim3(2, SPLITK), 128>>>();
    ppool_k<<<PBLK, 256>>>(batch);
    final_k<<<NG, 256>>>(gattr, W2l, b2, W2r, Wf1, bf1, Wf2, bf2, out);
}

// round 4
// speedup vs baseline: 2.0843x; 2.0843x over previous
#include <cuda_runtime.h>
#include <cuda_bf16.h>
#include <cstdint>

#define NN   100000
#define NE   1600000
#define NG   64
#define DIN  128
#define HID  256
#define NB1  391          // ceil(NN/256)
#define G2BLK 125         // gemm2 split-K blocks
#define G2CH  800         // 125*800 = 100000 exactly
#define PBLK   296
#define PCH    338        // 296*338 >= NN

// ------------- static device scratch (no allocations allowed) -------------
__device__ __align__(16) __nv_bfloat16 g_xb[(size_t)NN * DIN];     // 25.6 MB
__device__ __align__(16) __nv_bfloat16 g_agg1b[(size_t)NN * DIN];  // 25.6 MB
__device__ __align__(16) __nv_bfloat16 g_h1b[(size_t)NN * HID];    // 51.2 MB
__device__ __align__(16) __nv_bfloat16 g_Wcat[2 * DIN * HID];      // 128 KB
__device__ __align__(16) float g_coef[(size_t)NN * NG];            // 25.6 MB
__device__ __align__(16) float g_Qa[NG * HID];
__device__ __align__(16) float g_P[NG * HID];
__device__ int   g_cnt[NN];
__device__ int   g_eoff[NN];
__device__ int   g_wpos[NN];
__device__ int   g_bsum[NB1];
__device__ int   g_boff[512];
__device__ int   g_ncnt[NG];
__device__ float g_invcnt[NN];
__device__ float g_invng[NG];
__device__ int   g_esrc[NE];

// --------------------------- helpers ---------------------------
__device__ __forceinline__ uint32_t pkbf(float lo, float hi) {
    __nv_bfloat162 h = __float22bfloat162_rn(make_float2(lo, hi));
    return *(uint32_t*)&h;
}
__device__ __forceinline__ uint32_t s2u(const void* p) {
    return (uint32_t)__cvta_generic_to_shared(p);
}
__device__ __forceinline__ void ldmA(uint32_t r[4], uint32_t addr) {
    asm volatile("ldmatrix.sync.aligned.m8n8.x4.shared.b16 {%0,%1,%2,%3}, [%4];"
                 : "=r"(r[0]), "=r"(r[1]), "=r"(r[2]), "=r"(r[3]) : "r"(addr));
}
__device__ __forceinline__ void ldmT(uint32_t r[4], uint32_t addr) {
    asm volatile("ldmatrix.sync.aligned.m8n8.x4.trans.shared.b16 {%0,%1,%2,%3}, [%4];"
                 : "=r"(r[0]), "=r"(r[1]), "=r"(r[2]), "=r"(r[3]) : "r"(addr));
}
__device__ __forceinline__ void mma16816(float c[4], const uint32_t a[4], const uint32_t b[2]) {
    asm volatile("mma.sync.aligned.m16n8k16.row.col.f32.bf16.bf16.f32 "
                 "{%0,%1,%2,%3}, {%4,%5,%6,%7}, {%8,%9}, {%0,%1,%2,%3};"
                 : "+f"(c[0]), "+f"(c[1]), "+f"(c[2]), "+f"(c[3])
                 : "r"(a[0]), "r"(a[1]), "r"(a[2]), "r"(a[3]), "r"(b[0]), "r"(b[1]));
}

// --------------------------- zero scratch ---------------------------
__global__ void zero_all() {
    size_t i = (size_t)blockIdx.x * blockDim.x + threadIdx.x;
    size_t stride = (size_t)gridDim.x * blockDim.x;
    float4 z = make_float4(0.f, 0.f, 0.f, 0.f);
    for (size_t j = i; j < (size_t)NN * NG / 4; j += stride)
        ((float4*)g_coef)[j] = z;
    for (size_t j = i; j < NN; j += stride) g_cnt[j] = 0;
    for (size_t j = i; j < NG * HID; j += stride) { g_Qa[j] = 0.f; g_P[j] = 0.f; }
    if (i < NG) g_ncnt[i] = 0;
}

// --------------------------- convert x -> bf16 ---------------------------
__global__ void convx_k(const float* __restrict__ x) {
    size_t i = (size_t)blockIdx.x * blockDim.x + threadIdx.x;
    if (i < (size_t)NN * DIN / 4) {
        float4 v = ((const float4*)x)[i];
        uint2 o = make_uint2(pkbf(v.x, v.y), pkbf(v.z, v.w));
        ((uint2*)g_xb)[i] = o;
    }
}

// --------------------------- build Wcat = [W1r ; W1l] in bf16 ---------------------------
__global__ void prepw_k(const float* __restrict__ W1l, const float* __restrict__ W1r) {
    int i = blockIdx.x * blockDim.x + threadIdx.x;  // float4 index over 256x256
    if (i < 2 * DIN * HID / 4) {
        int e = i * 4;
        int k = e >> 8, n = e & 255;
        const float* src = (k < DIN) ? &W1r[k * HID + n] : &W1l[(k - DIN) * HID + n];
        float4 v = *(const float4*)src;
        ((uint2*)g_Wcat)[i] = make_uint2(pkbf(v.x, v.y), pkbf(v.z, v.w));
    }
}

// --------------------------- degree count ---------------------------
__global__ void count_k(const int* __restrict__ ei) {
    int e = blockIdx.x * blockDim.x + threadIdx.x;
    if (e < NE) {
        int d = ei[NE + e];
        if ((unsigned)d < NN) atomicAdd(&g_cnt[d], 1);
    }
}

// --------------------------- per-graph node count ---------------------------
__global__ void gcount_k(const int* __restrict__ batch) {
    int i = blockIdx.x * blockDim.x + threadIdx.x;
    if (i < NN) {
        int g = batch[i];
        if ((unsigned)g < NG) atomicAdd(&g_ncnt[g], 1);
    }
}

// --------------------------- exclusive scan of degrees ---------------------------
__global__ void scan1_k() {
    __shared__ int sh[256];
    int t = threadIdx.x;
    int i = blockIdx.x * 256 + t;
    int val = (i < NN) ? g_cnt[i] : 0;
    sh[t] = val;
    __syncthreads();
    for (int d = 1; d < 256; d <<= 1) {
        int add = (t >= d) ? sh[t - d] : 0;
        __syncthreads();
        sh[t] += add;
        __syncthreads();
    }
    if (i < NN) g_eoff[i] = sh[t] - val;
    if (t == 255) g_bsum[blockIdx.x] = sh[255];
}

__global__ void scan2_k() {
    __shared__ int sh[512];
    int t = threadIdx.x;
    int val = (t < NB1) ? g_bsum[t] : 0;
    sh[t] = val;
    __syncthreads();
    for (int d = 1; d < 512; d <<= 1) {
        int add = (t >= d) ? sh[t - d] : 0;
        __syncthreads();
        sh[t] += add;
        __syncthreads();
    }
    g_boff[t] = sh[t] - val;
}

__global__ void scan3_k() {
    int i = blockIdx.x * blockDim.x + threadIdx.x;
    if (i < NN) {
        int off = g_eoff[i] + g_boff[i >> 8];
        g_eoff[i] = off;
        g_wpos[i] = off;
        g_invcnt[i] = 1.0f / fmaxf((float)g_cnt[i], 1.0f);
    }
    if (i < NG) g_invng[i] = 1.0f / fmaxf((float)g_ncnt[i], 1.0f);
}

// --------------------------- counting-sort placement (CSR by dst) ---------------------------
__global__ void place_k(const int* __restrict__ ei) {
    int e = blockIdx.x * blockDim.x + threadIdx.x;
    if (e < NE) {
        int s = ei[e];
        int d = ei[NE + e];
        if ((unsigned)s < NN && (unsigned)d < NN) {
            int p = atomicAdd(&g_wpos[d], 1);
            g_esrc[p] = s;
        }
    }
}

// --------------------------- layer-1 mean aggregation (warp per node, bf16 gather) ---------------------------
__global__ void agg1_k() {
    int gtid = blockIdx.x * blockDim.x + threadIdx.x;
    int v = gtid >> 5;
    if (v >= NN) return;
    int lane = gtid & 31;
    int start = g_eoff[v];
    int end = (v + 1 < NN) ? g_eoff[v + 1] : NE;
    float a0 = 0.f, a1 = 0.f, a2 = 0.f, a3 = 0.f;
    const uint2* xb2 = (const uint2*)g_xb;
    for (int i = start; i < end; ++i) {
        int s = g_esrc[i];
        uint2 t = xb2[(size_t)s * (DIN / 4) + lane];
        __nv_bfloat162 p0 = *(__nv_bfloat162*)&t.x;
        __nv_bfloat162 p1 = *(__nv_bfloat162*)&t.y;
        a0 += __bfloat162float(p0.x); a1 += __bfloat162float(p0.y);
        a2 += __bfloat162float(p1.x); a3 += __bfloat162float(p1.y);
    }
    float w = g_invcnt[v];
    uint2 o = make_uint2(pkbf(a0 * w, a1 * w), pkbf(a2 * w, a3 * w));
    ((uint2*)g_agg1b)[(size_t)v * (DIN / 4) + lane] = o;
}

// --------------------------- coef build (scalar edge pass) ---------------------------
__global__ void coef_k(const int* __restrict__ ei,
                       const int* __restrict__ batch) {
    int e = blockIdx.x * blockDim.x + threadIdx.x;
    if (e < NE) {
        int s = ei[e];
        int d = ei[NE + e];
        if ((unsigned)s < NN && (unsigned)d < NN) {
            int g = batch[d];
            atomicAdd(&g_coef[(size_t)s * NG + g], g_invcnt[d]);
        }
    }
}

// --------------------------- GEMM1 (bf16 mma): h1 = relu([x|agg1]@Wcat + b1) ---------------------------
// block: 256 thr = 8 warps (2m x 4n). tile M=64, N=256, K=256 (8 steps of 32).
__global__ void __launch_bounds__(256) gemm1_k(const float* __restrict__ b1) {
    __shared__ __align__(16) __nv_bfloat16 As[64 * 40];
    __shared__ __align__(16) __nv_bfloat16 Bs[32 * 264];
    int tid = threadIdx.x;
    int wid = tid >> 5, lane = tid & 31;
    int m0 = blockIdx.x * 64;
    int mw = (wid & 1) * 32;
    int nw = (wid >> 1) * 64;

    float acc[2][8][4];
#pragma unroll
    for (int i = 0; i < 2; i++)
#pragma unroll
        for (int j = 0; j < 8; j++)
#pragma unroll
            for (int q = 0; q < 4; q++) acc[i][j][q] = 0.f;

    int arow = tid >> 2;          // 0..63
    int acol = (tid & 3) * 8;     // 0..24
    int gr = m0 + arow;

    uint4 pa;
    uint4 pb[4];

    // prefetch step 0
    {
        int k = acol;  // step 0 -> xb
        pa = (gr < NN) ? *(const uint4*)&g_xb[(size_t)gr * DIN + k] : make_uint4(0, 0, 0, 0);
#pragma unroll
        for (int j = 0; j < 4; j++) {
            int c = tid + 256 * j;
            int row = c >> 5, col = (c & 31) * 8;
            pb[j] = *(const uint4*)&g_Wcat[(size_t)row * HID + col];
        }
    }

    for (int s = 0; s < 8; s++) {
        __syncthreads();
        *(uint4*)&As[arow * 40 + acol] = pa;
#pragma unroll
        for (int j = 0; j < 4; j++) {
            int c = tid + 256 * j;
            int row = c >> 5, col = (c & 31) * 8;
            *(uint4*)&Bs[row * 264 + col] = pb[j];
        }
        __syncthreads();

        if (s + 1 < 8) {
            int kb = (s + 1) * 32;
            int k = kb + acol;
            if (gr < NN) {
                const __nv_bfloat16* src = (k < DIN) ? &g_xb[(size_t)gr * DIN + k]
                                                     : &g_agg1b[(size_t)gr * DIN + (k - DIN)];
                pa = *(const uint4*)src;
            } else pa = make_uint4(0, 0, 0, 0);
#pragma unroll
            for (int j = 0; j < 4; j++) {
                int c = tid + 256 * j;
                int row = c >> 5, col = (c & 31) * 8;
                pb[j] = *(const uint4*)&g_Wcat[(size_t)(kb + row) * HID + col];
            }
        }

#pragma unroll
        for (int ks = 0; ks < 32; ks += 16) {
            uint32_t af[2][4];
#pragma unroll
            for (int mi = 0; mi < 2; mi++) {
                uint32_t addr = s2u(&As[(mw + mi * 16 + (lane & 15)) * 40 + ks + (lane >> 4) * 8]);
                ldmA(af[mi], addr);
            }
#pragma unroll
            for (int nf = 0; nf < 4; nf++) {
                uint32_t bf[4];
                uint32_t addr = s2u(&Bs[(ks + ((lane >> 3) & 1) * 8 + (lane & 7)) * 264 +
                                        nw + nf * 16 + (lane >> 4) * 8]);
                ldmT(bf, addr);
#pragma unroll
                for (int mi = 0; mi < 2; mi++) {
                    mma16816(acc[mi][nf * 2], af[mi], bf);
                    mma16816(acc[mi][nf * 2 + 1], af[mi], bf + 2);
                }
            }
        }
    }

    // epilogue: bias + relu -> bf16
    uint32_t* h1u = (uint32_t*)g_h1b;
#pragma unroll
    for (int mi = 0; mi < 2; mi++) {
#pragma unroll
        for (int nf = 0; nf < 8; nf++) {
            int col = nw + nf * 8 + (lane & 3) * 2;
            float bx = b1[col], by = b1[col + 1];
            int row = m0 + mw + mi * 16 + (lane >> 2);
            if (row < NN)
                h1u[((size_t)row * HID + col) >> 1] =
                    pkbf(fmaxf(acc[mi][nf][0] + bx, 0.f), fmaxf(acc[mi][nf][1] + by, 0.f));
            int row2 = row + 8;
            if (row2 < NN)
                h1u[((size_t)row2 * HID + col) >> 1] =
                    pkbf(fmaxf(acc[mi][nf][2] + bx, 0.f), fmaxf(acc[mi][nf][3] + by, 0.f));
        }
    }
}

// --------------------------- GEMM2 (bf16 mma): Qa = coef^T @ h1 (split-K, atomics) ---------------------------
// block: 256 thr = 8 warps, each warp n32. tile M=64, N=256, K chunk 800 (25 steps of 32).
__global__ void __launch_bounds__(256) gemm2_k() {
    __shared__ __align__(16) __nv_bfloat16 Ks[32 * 72];
    __shared__ __align__(16) __nv_bfloat16 Bs[32 * 264];
    int tid = threadIdx.x;
    int wid = tid >> 5, lane = tid & 31;
    int nb = blockIdx.x * G2CH;
    int n0w = wid * 32;

    float acc[4][4][4];
#pragma unroll
    for (int i = 0; i < 4; i++)
#pragma unroll
        for (int j = 0; j < 4; j++)
#pragma unroll
            for (int q = 0; q < 4; q++) acc[i][j][q] = 0.f;

    int cnode = tid >> 3;        // 0..31
    int cg = (tid & 7) * 8;      // 0..56

    float4 cf0, cf1;
    uint4 hb[4];

    // prefetch step 0
    {
        size_t base = (size_t)(nb + cnode) * NG + cg;
        cf0 = *(const float4*)&g_coef[base];
        cf1 = *(const float4*)&g_coef[base + 4];
#pragma unroll
        for (int j = 0; j < 4; j++) {
            int c = tid + 256 * j;
            int row = c >> 5, col = (c & 31) * 8;
            hb[j] = *(const uint4*)&g_h1b[(size_t)(nb + row) * HID + col];
        }
    }

    for (int s = 0; s < 25; s++) {
        __syncthreads();
        {
            uint4 kv = make_uint4(pkbf(cf0.x, cf0.y), pkbf(cf0.z, cf0.w),
                                  pkbf(cf1.x, cf1.y), pkbf(cf1.z, cf1.w));
            *(uint4*)&Ks[cnode * 72 + cg] = kv;
#pragma unroll
            for (int j = 0; j < 4; j++) {
                int c = tid + 256 * j;
                int row = c >> 5, col = (c & 31) * 8;
                *(uint4*)&Bs[row * 264 + col] = hb[j];
            }
        }
        __syncthreads();

        if (s + 1 < 25) {
            int kb = nb + (s + 1) * 32;
            size_t base = (size_t)(kb + cnode) * NG + cg;
            cf0 = *(const float4*)&g_coef[base];
            cf1 = *(const float4*)&g_coef[base + 4];
#pragma unroll
            for (int j = 0; j < 4; j++) {
                int c = tid + 256 * j;
                int row = c >> 5, col = (c & 31) * 8;
                hb[j] = *(const uint4*)&g_h1b[(size_t)(kb + row) * HID + col];
            }
        }

#pragma unroll
        for (int ks = 0; ks < 32; ks += 16) {
            uint32_t af[4][4];
#pragma unroll
            for (int mi = 0; mi < 4; mi++) {
                uint32_t addr = s2u(&Ks[(ks + ((lane >> 4) & 1) * 8 + (lane & 7)) * 72 +
                                        mi * 16 + ((lane >> 3) & 1) * 8]);
                ldmT(af[mi], addr);
            }
#pragma unroll
            for (int nf = 0; nf < 2; nf++) {
                uint32_t bf[4];
                uint32_t addr = s2u(&Bs[(ks + ((lane >> 3) & 1) * 8 + (lane & 7)) * 264 +
                                        n0w + nf * 16 + (lane >> 4) * 8]);
                ldmT(bf, addr);
#pragma unroll
                for (int mi = 0; mi < 4; mi++) {
                    mma16816(acc[mi][nf * 2], af[mi], bf);
                    mma16816(acc[mi][nf * 2 + 1], af[mi], bf + 2);
                }
            }
        }
    }

#pragma unroll
    for (int mi = 0; mi < 4; mi++) {
#pragma unroll
        for (int nf = 0; nf < 4; nf++) {
            int col = n0w + nf * 8 + (lane & 3) * 2;
            int row = mi * 16 + (lane >> 2);
            atomicAdd(&g_Qa[row * HID + col], acc[mi][nf][0]);
            atomicAdd(&g_Qa[row * HID + col + 1], acc[mi][nf][1]);
            atomicAdd(&g_Qa[(row + 8) * HID + col], acc[mi][nf][2]);
            atomicAdd(&g_Qa[(row + 8) * HID + col + 1], acc[mi][nf][3]);
        }
    }
}

// --------------------------- P: segmented sum of h1 over sorted batch ---------------------------
__global__ void ppool_k(const int* __restrict__ batch) {
    int n0 = blockIdx.x * PCH;
    if (n0 >= NN) return;
    int n1 = n0 + PCH;
    if (n1 > NN) n1 = NN;
    int d = threadIdx.x;
    float ps = 0.f;
    int curg = batch[n0];
    for (int v = n0; v < n1; v++) {
        int g = batch[v];
        if (g != curg) {
            atomicAdd(&g_P[curg * HID + d], ps);
            ps = 0.f;
            curg = g;
        }
        ps += __bfloat162float(g_h1b[(size_t)v * HID + d]);
    }
    atomicAdd(&g_P[curg * HID + d], ps);
}

// --------------------------- final: layer2 fold + pool + MLP head ---------------------------
__global__ void final_k(const float* __restrict__ gattr,
                        const float* __restrict__ W2l, const float* __restrict__ b2,
                        const float* __restrict__ W2r,
                        const float* __restrict__ Wf1, const float* __restrict__ bf1,
                        const float* __restrict__ Wf2, const float* __restrict__ bf2,
                        float* __restrict__ out) {
    __shared__ float q[HID], p[HID], pooled[HID], red[HID];
    int g = blockIdx.x, j = threadIdx.x;
    q[j] = g_Qa[g * HID + j];
    p[j] = g_P[g * HID + j];
    __syncthreads();
    float acc = 0.f;
    for (int k = 0; k < HID; k++)
        acc += q[k] * W2l[k * HID + j] + p[k] * W2r[k * HID + j];
    pooled[j] = g_invng[g] * acc + b2[j];
    __syncthreads();
    float a2 = bf1[j];
    for (int k = 0; k < HID; k++)
        a2 += pooled[k] * Wf1[k * HID + j];
    for (int a = 0; a < 8; a++)
        a2 += gattr[g * 8 + a] * Wf1[(HID + a) * HID + j];
    float t1 = fmaxf(a2, 0.f);
    red[j] = t1 * Wf2[j];
    __syncthreads();
    for (int s = 128; s > 0; s >>= 1) {
        if (j < s) red[j] += red[j + s];
        __syncthreads();
    }
    if (j == 0) out[g] = red[0] + bf2[0];
}

// --------------------------- launch ---------------------------
extern "C" void kernel_launch(void* const* d_in, const int* in_sizes, int n_in,
                              void* d_out, int out_size) {
    const float* x = (const float*)d_in[0];
    const int* ei = (const int*)d_in[1];
    const int* batch = (const int*)d_in[2];
    const float* gattr = (const float*)d_in[3];
    const float* W1l = (const float*)d_in[4];
    const float* b1  = (const float*)d_in[5];
    const float* W1r = (const float*)d_in[6];
    const float* W2l = (const float*)d_in[7];
    const float* b2  = (const float*)d_in[8];
    const float* W2r = (const float*)d_in[9];
    const float* Wf1 = (const float*)d_in[10];
    const float* bf1 = (const float*)d_in[11];
    const float* Wf2 = (const float*)d_in[12];
    const float* bf2 = (const float*)d_in[13];
    float* out = (float*)d_out;

    zero_all<<<2048, 256>>>();
    convx_k<<<(NN * DIN / 4 + 255) / 256, 256>>>(x);
    prepw_k<<<(2 * DIN * HID / 4 + 255) / 256, 256>>>(W1l, W1r);
    count_k<<<(NE + 255) / 256, 256>>>(ei);
    gcount_k<<<(NN + 255) / 256, 256>>>(batch);
    scan1_k<<<NB1, 256>>>();
    scan2_k<<<1, 512>>>();
    scan3_k<<<NB1, 256>>>();
    place_k<<<(NE + 255) / 256, 256>>>(ei);
    agg1_k<<<(NN * 32 + 255) / 256, 256>>>();
    coef_k<<<(NE + 255) / 256, 256>>>(ei, batch);
    gemm1_k<<<(NN + 63) / 64, 256>>>(b1);
    gemm2_k<<<G2BLK, 256>>>();
    ppool_k<<<PBLK, 256>>>(batch);
    final_k<<<NG, 256>>>(gattr, W2l, b2, W2r, Wf1, bf1, Wf2, bf2, out);
}

// round 5
// speedup vs baseline: 2.4018x; 1.1523x over previous
#include <cuda_runtime.h>
#include <cuda_bf16.h>
#include <cstdint>

#define NN   100000
#define NE   1600000
#define NG   64
#define DIN  128
#define HID  256
#define NB1  391          // ceil(NN/256)
#define G2BLK 125         // gemm2 split-K blocks
#define G2CH  800         // 125*800 = 100000 exactly
#define PBLK   296
#define PCH    338        // 296*338 >= NN

// ------------- static device scratch (no allocations allowed) -------------
__device__ __align__(16) __nv_bfloat16 g_xb[(size_t)NN * DIN];     // 25.6 MB
__device__ __align__(16) __nv_bfloat16 g_agg1b[(size_t)NN * DIN];  // 25.6 MB
__device__ __align__(16) __nv_bfloat16 g_h1b[(size_t)NN * HID];    // 51.2 MB
__device__ __align__(16) __nv_bfloat16 g_Wcat[2 * DIN * HID];      // 128 KB
__device__ __align__(16) float g_coef[(size_t)NN * NG];            // 25.6 MB
__device__ __align__(16) float g_Qa[NG * HID];
__device__ __align__(16) float g_P[NG * HID];
__device__ __align__(16) int g_cnt[NN];
__device__ int   g_eoff[NN];
__device__ int   g_wpos[NN];
__device__ int   g_bsum[NB1];
__device__ int   g_boff[512];
__device__ int   g_ncnt[NG];
__device__ float g_invcnt[NN];
__device__ float g_invng[NG];
__device__ int   g_esrc[NE];

// --------------------------- helpers ---------------------------
__device__ __forceinline__ uint32_t pkbf(float lo, float hi) {
    __nv_bfloat162 h = __float22bfloat162_rn(make_float2(lo, hi));
    return *(uint32_t*)&h;
}
__device__ __forceinline__ uint32_t s2u(const void* p) {
    return (uint32_t)__cvta_generic_to_shared(p);
}
__device__ __forceinline__ void ldmA(uint32_t r[4], uint32_t addr) {
    asm volatile("ldmatrix.sync.aligned.m8n8.x4.shared.b16 {%0,%1,%2,%3}, [%4];"
                 : "=r"(r[0]), "=r"(r[1]), "=r"(r[2]), "=r"(r[3]) : "r"(addr));
}
__device__ __forceinline__ void ldmT(uint32_t r[4], uint32_t addr) {
    asm volatile("ldmatrix.sync.aligned.m8n8.x4.trans.shared.b16 {%0,%1,%2,%3}, [%4];"
                 : "=r"(r[0]), "=r"(r[1]), "=r"(r[2]), "=r"(r[3]) : "r"(addr));
}
__device__ __forceinline__ void mma16816(float c[4], const uint32_t a[4], const uint32_t b[2]) {
    asm volatile("mma.sync.aligned.m16n8k16.row.col.f32.bf16.bf16.f32 "
                 "{%0,%1,%2,%3}, {%4,%5,%6,%7}, {%8,%9}, {%0,%1,%2,%3};"
                 : "+f"(c[0]), "+f"(c[1]), "+f"(c[2]), "+f"(c[3])
                 : "r"(a[0]), "r"(a[1]), "r"(a[2]), "r"(a[3]), "r"(b[0]), "r"(b[1]));
}

// ---------------- init: zero scratch + convert x + build Wcat ----------------
__global__ void init_k(const float* __restrict__ x,
                       const float* __restrict__ W1l, const float* __restrict__ W1r) {
    size_t i = (size_t)blockIdx.x * blockDim.x + threadIdx.x;
    size_t stride = (size_t)gridDim.x * blockDim.x;
    float4 z = make_float4(0.f, 0.f, 0.f, 0.f);
    for (size_t j = i; j < (size_t)NN * NG / 4; j += stride)
        ((float4*)g_coef)[j] = z;
    for (size_t j = i; j < NN / 4; j += stride)
        ((int4*)g_cnt)[j] = make_int4(0, 0, 0, 0);
    for (size_t j = i; j < NG * HID / 4; j += stride) {
        ((float4*)g_Qa)[j] = z;
        ((float4*)g_P)[j] = z;
    }
    if (i < NG) g_ncnt[i] = 0;
    for (size_t j = i; j < (size_t)NN * DIN / 4; j += stride) {
        float4 v = ((const float4*)x)[j];
        ((uint2*)g_xb)[j] = make_uint2(pkbf(v.x, v.y), pkbf(v.z, v.w));
    }
    for (size_t j = i; j < (size_t)2 * DIN * HID / 4; j += stride) {
        size_t e = j * 4;
        int k = (int)(e >> 8), n = (int)(e & 255);
        const float* src = (k < DIN) ? &W1r[k * HID + n] : &W1l[(k - DIN) * HID + n];
        float4 v = *(const float4*)src;
        ((uint2*)g_Wcat)[j] = make_uint2(pkbf(v.x, v.y), pkbf(v.z, v.w));
    }
}

// ---------------- degree count + per-graph node count (fused, int4) ----------------
__global__ void cnt_k(const int* __restrict__ ei, const int* __restrict__ batch) {
    int i = blockIdx.x * blockDim.x + threadIdx.x;
    int stride = gridDim.x * blockDim.x;
    const int4* d4 = (const int4*)(ei + NE);
    for (int j = i; j < NE / 4; j += stride) {
        int4 d = d4[j];
        atomicAdd(&g_cnt[d.x], 1);
        atomicAdd(&g_cnt[d.y], 1);
        atomicAdd(&g_cnt[d.z], 1);
        atomicAdd(&g_cnt[d.w], 1);
    }
    const int4* b4 = (const int4*)batch;
    for (int j = i; j < NN / 4; j += stride) {
        int4 b = b4[j];
        if (b.x == b.w) {                 // sorted: whole quad same graph (common case)
            atomicAdd(&g_ncnt[b.x], 4);
        } else {
            atomicAdd(&g_ncnt[b.x], 1);
            atomicAdd(&g_ncnt[b.y], 1);
            atomicAdd(&g_ncnt[b.z], 1);
            atomicAdd(&g_ncnt[b.w], 1);
        }
    }
}

// --------------------------- exclusive scan of degrees ---------------------------
__global__ void scan1_k() {
    __shared__ int sh[256];
    int t = threadIdx.x;
    int i = blockIdx.x * 256 + t;
    int val = (i < NN) ? g_cnt[i] : 0;
    sh[t] = val;
    __syncthreads();
    for (int d = 1; d < 256; d <<= 1) {
        int add = (t >= d) ? sh[t - d] : 0;
        __syncthreads();
        sh[t] += add;
        __syncthreads();
    }
    if (i < NN) g_eoff[i] = sh[t] - val;
    if (t == 255) g_bsum[blockIdx.x] = sh[255];
}

__global__ void scan2_k() {
    __shared__ int sh[512];
    int t = threadIdx.x;
    int val = (t < NB1) ? g_bsum[t] : 0;
    sh[t] = val;
    __syncthreads();
    for (int d = 1; d < 512; d <<= 1) {
        int add = (t >= d) ? sh[t - d] : 0;
        __syncthreads();
        sh[t] += add;
        __syncthreads();
    }
    g_boff[t] = sh[t] - val;
}

__global__ void scan3_k() {
    int i = blockIdx.x * blockDim.x + threadIdx.x;
    if (i < NN) {
        int off = g_eoff[i] + g_boff[i >> 8];
        g_eoff[i] = off;
        g_wpos[i] = off;
        g_invcnt[i] = 1.0f / fmaxf((float)g_cnt[i], 1.0f);
    }
    if (i < NG) g_invng[i] = 1.0f / fmaxf((float)g_ncnt[i], 1.0f);
}

// ---------------- CSR placement + coef build (fused: one ei read) ----------------
__global__ void placecoef_k(const int* __restrict__ ei, const int* __restrict__ batch) {
    int e = blockIdx.x * blockDim.x + threadIdx.x;
    if (e < NE) {
        int s = ei[e];
        int d = ei[NE + e];
        int p = atomicAdd(&g_wpos[d], 1);
        g_esrc[p] = s;
        int g = batch[d];
        atomicAdd(&g_coef[(size_t)s * NG + g], g_invcnt[d]);
    }
}

// ---------------- layer-1 mean aggregation (warp/node, unroll-4 for MLP) ----------------
__global__ void agg1_k() {
    int gtid = blockIdx.x * blockDim.x + threadIdx.x;
    int v = gtid >> 5;
    if (v >= NN) return;
    int lane = gtid & 31;
    int start = g_eoff[v];
    int end = (v + 1 < NN) ? g_eoff[v + 1] : NE;
    float a0 = 0.f, a1 = 0.f, a2 = 0.f, a3 = 0.f;
    const uint2* xb2 = (const uint2*)g_xb;
    int i = start;
    for (; i + 4 <= end; i += 4) {
        int s0 = g_esrc[i], s1 = g_esrc[i + 1], s2 = g_esrc[i + 2], s3 = g_esrc[i + 3];
        uint2 t0 = xb2[(size_t)s0 * (DIN / 4) + lane];
        uint2 t1 = xb2[(size_t)s1 * (DIN / 4) + lane];
        uint2 t2 = xb2[(size_t)s2 * (DIN / 4) + lane];
        uint2 t3 = xb2[(size_t)s3 * (DIN / 4) + lane];
#define ACC(t)                                              \
        {                                                   \
            __nv_bfloat162 p0 = *(__nv_bfloat162*)&(t).x;   \
            __nv_bfloat162 p1 = *(__nv_bfloat162*)&(t).y;   \
            a0 += __bfloat162float(p0.x);                   \
            a1 += __bfloat162float(p0.y);                   \
            a2 += __bfloat162float(p1.x);                   \
            a3 += __bfloat162float(p1.y);                   \
        }
        ACC(t0) ACC(t1) ACC(t2) ACC(t3)
    }
    for (; i < end; ++i) {
        uint2 t = xb2[(size_t)g_esrc[i] * (DIN / 4) + lane];
        ACC(t)
    }
#undef ACC
    float w = g_invcnt[v];
    uint2 o = make_uint2(pkbf(a0 * w, a1 * w), pkbf(a2 * w, a3 * w));
    ((uint2*)g_agg1b)[(size_t)v * (DIN / 4) + lane] = o;
}

// --------------------------- GEMM1 (bf16 mma): h1 = relu([x|agg1]@Wcat + b1) ---------------------------
__global__ void __launch_bounds__(256) gemm1_k(const float* __restrict__ b1) {
    __shared__ __align__(16) __nv_bfloat16 As[64 * 40];
    __shared__ __align__(16) __nv_bfloat16 Bs[32 * 264];
    int tid = threadIdx.x;
    int wid = tid >> 5, lane = tid & 31;
    int m0 = blockIdx.x * 64;
    int mw = (wid & 1) * 32;
    int nw = (wid >> 1) * 64;

    float acc[2][8][4];
#pragma unroll
    for (int i = 0; i < 2; i++)
#pragma unroll
        for (int j = 0; j < 8; j++)
#pragma unroll
            for (int q = 0; q < 4; q++) acc[i][j][q] = 0.f;

    int arow = tid >> 2;
    int acol = (tid & 3) * 8;
    int gr = m0 + arow;

    uint4 pa;
    uint4 pb[4];

    {
        int k = acol;
        pa = (gr < NN) ? *(const uint4*)&g_xb[(size_t)gr * DIN + k] : make_uint4(0, 0, 0, 0);
#pragma unroll
        for (int j = 0; j < 4; j++) {
            int c = tid + 256 * j;
            int row = c >> 5, col = (c & 31) * 8;
            pb[j] = *(const uint4*)&g_Wcat[(size_t)row * HID + col];
        }
    }

    for (int s = 0; s < 8; s++) {
        __syncthreads();
        *(uint4*)&As[arow * 40 + acol] = pa;
#pragma unroll
        for (int j = 0; j < 4; j++) {
            int c = tid + 256 * j;
            int row = c >> 5, col = (c & 31) * 8;
            *(uint4*)&Bs[row * 264 + col] = pb[j];
        }
        __syncthreads();

        if (s + 1 < 8) {
            int kb = (s + 1) * 32;
            int k = kb + acol;
            if (gr < NN) {
                const __nv_bfloat16* src = (k < DIN) ? &g_xb[(size_t)gr * DIN + k]
                                                     : &g_agg1b[(size_t)gr * DIN + (k - DIN)];
                pa = *(const uint4*)src;
            } else pa = make_uint4(0, 0, 0, 0);
#pragma unroll
            for (int j = 0; j < 4; j++) {
                int c = tid + 256 * j;
                int row = c >> 5, col = (c & 31) * 8;
                pb[j] = *(const uint4*)&g_Wcat[(size_t)(kb + row) * HID + col];
            }
        }

#pragma unroll
        for (int ks = 0; ks < 32; ks += 16) {
            uint32_t af[2][4];
#pragma unroll
            for (int mi = 0; mi < 2; mi++) {
                uint32_t addr = s2u(&As[(mw + mi * 16 + (lane & 15)) * 40 + ks + (lane >> 4) * 8]);
                ldmA(af[mi], addr);
            }
#pragma unroll
            for (int nf = 0; nf < 4; nf++) {
                uint32_t bf[4];
                uint32_t addr = s2u(&Bs[(ks + ((lane >> 3) & 1) * 8 + (lane & 7)) * 264 +
                                        nw + nf * 16 + (lane >> 4) * 8]);
                ldmT(bf, addr);
#pragma unroll
                for (int mi = 0; mi < 2; mi++) {
                    mma16816(acc[mi][nf * 2], af[mi], bf);
                    mma16816(acc[mi][nf * 2 + 1], af[mi], bf + 2);
                }
            }
        }
    }

    uint32_t* h1u = (uint32_t*)g_h1b;
#pragma unroll
    for (int mi = 0; mi < 2; mi++) {
#pragma unroll
        for (int nf = 0; nf < 8; nf++) {
            int col = nw + nf * 8 + (lane & 3) * 2;
            float bx = b1[col], by = b1[col + 1];
            int row = m0 + mw + mi * 16 + (lane >> 2);
            if (row < NN)
                h1u[((size_t)row * HID + col) >> 1] =
                    pkbf(fmaxf(acc[mi][nf][0] + bx, 0.f), fmaxf(acc[mi][nf][1] + by, 0.f));
            int row2 = row + 8;
            if (row2 < NN)
                h1u[((size_t)row2 * HID + col) >> 1] =
                    pkbf(fmaxf(acc[mi][nf][2] + bx, 0.f), fmaxf(acc[mi][nf][3] + by, 0.f));
        }
    }
}

// --------------------------- GEMM2 (bf16 mma): Qa = coef^T @ h1 (split-K, atomics) ---------------------------
__global__ void __launch_bounds__(256) gemm2_k() {
    __shared__ __align__(16) __nv_bfloat16 Ks[32 * 72];
    __shared__ __align__(16) __nv_bfloat16 Bs[32 * 264];
    int tid = threadIdx.x;
    int wid = tid >> 5, lane = tid & 31;
    int nb = blockIdx.x * G2CH;
    int n0w = wid * 32;

    float acc[4][4][4];
#pragma unroll
    for (int i = 0; i < 4; i++)
#pragma unroll
        for (int j = 0; j < 4; j++)
#pragma unroll
            for (int q = 0; q < 4; q++) acc[i][j][q] = 0.f;

    int cnode = tid >> 3;
    int cg = (tid & 7) * 8;

    float4 cf0, cf1;
    uint4 hb[4];

    {
        size_t base = (size_t)(nb + cnode) * NG + cg;
        cf0 = *(const float4*)&g_coef[base];
        cf1 = *(const float4*)&g_coef[base + 4];
#pragma unroll
        for (int j = 0; j < 4; j++) {
            int c = tid + 256 * j;
            int row = c >> 5, col = (c & 31) * 8;
            hb[j] = *(const uint4*)&g_h1b[(size_t)(nb + row) * HID + col];
        }
    }

    for (int s = 0; s < 25; s++) {
        __syncthreads();
        {
            uint4 kv = make_uint4(pkbf(cf0.x, cf0.y), pkbf(cf0.z, cf0.w),
                                  pkbf(cf1.x, cf1.y), pkbf(cf1.z, cf1.w));
            *(uint4*)&Ks[cnode * 72 + cg] = kv;
#pragma unroll
            for (int j = 0; j < 4; j++) {
                int c = tid + 256 * j;
                int row = c >> 5, col = (c & 31) * 8;
                *(uint4*)&Bs[row * 264 + col] = hb[j];
            }
        }
        __syncthreads();

        if (s + 1 < 25) {
            int kb = nb + (s + 1) * 32;
            size_t base = (size_t)(kb + cnode) * NG + cg;
            cf0 = *(const float4*)&g_coef[base];
            cf1 = *(const float4*)&g_coef[base + 4];
#pragma unroll
            for (int j = 0; j < 4; j++) {
                int c = tid + 256 * j;
                int row = c >> 5, col = (c & 31) * 8;
                hb[j] = *(const uint4*)&g_h1b[(size_t)(kb + row) * HID + col];
            }
        }

#pragma unroll
        for (int ks = 0; ks < 32; ks += 16) {
            uint32_t af[4][4];
#pragma unroll
            for (int mi = 0; mi < 4; mi++) {
                uint32_t addr = s2u(&Ks[(ks + ((lane >> 4) & 1) * 8 + (lane & 7)) * 72 +
                                        mi * 16 + ((lane >> 3) & 1) * 8]);
                ldmT(af[mi], addr);
            }
#pragma unroll
            for (int nf = 0; nf < 2; nf++) {
                uint32_t bf[4];
                uint32_t addr = s2u(&Bs[(ks + ((lane >> 3) & 1) * 8 + (lane & 7)) * 264 +
                                        n0w + nf * 16 + (lane >> 4) * 8]);
                ldmT(bf, addr);
#pragma unroll
                for (int mi = 0; mi < 4; mi++) {
                    mma16816(acc[mi][nf * 2], af[mi], bf);
                    mma16816(acc[mi][nf * 2 + 1], af[mi], bf + 2);
                }
            }
        }
    }

#pragma unroll
    for (int mi = 0; mi < 4; mi++) {
#pragma unroll
        for (int nf = 0; nf < 4; nf++) {
            int col = n0w + nf * 8 + (lane & 3) * 2;
            int row = mi * 16 + (lane >> 2);
            atomicAdd(&g_Qa[row * HID + col], acc[mi][nf][0]);
            atomicAdd(&g_Qa[row * HID + col + 1], acc[mi][nf][1]);
            atomicAdd(&g_Qa[(row + 8) * HID + col], acc[mi][nf][2]);
            atomicAdd(&g_Qa[(row + 8) * HID + col + 1], acc[mi][nf][3]);
        }
    }
}

// --------------------------- P: segmented sum of h1 over sorted batch ---------------------------
__global__ void ppool_k(const int* __restrict__ batch) {
    int n0 = blockIdx.x * PCH;
    if (n0 >= NN) return;
    int n1 = n0 + PCH;
    if (n1 > NN) n1 = NN;
    int d = threadIdx.x;
    float ps = 0.f;
    int curg = batch[n0];
    for (int v = n0; v < n1; v++) {
        int g = batch[v];
        if (g != curg) {
            atomicAdd(&g_P[curg * HID + d], ps);
            ps = 0.f;
            curg = g;
        }
        ps += __bfloat162float(g_h1b[(size_t)v * HID + d]);
    }
    atomicAdd(&g_P[curg * HID + d], ps);
}

// --------------------------- final: layer2 fold + pool + MLP head ---------------------------
__global__ void final_k(const float* __restrict__ gattr,
                        const float* __restrict__ W2l, const float* __restrict__ b2,
                        const float* __restrict__ W2r,
                        const float* __restrict__ Wf1, const float* __restrict__ bf1,
                        const float* __restrict__ Wf2, const float* __restrict__ bf2,
                        float* __restrict__ out) {
    __shared__ float q[HID], p[HID], pooled[HID], red[HID];
    int g = blockIdx.x, j = threadIdx.x;
    q[j] = g_Qa[g * HID + j];
    p[j] = g_P[g * HID + j];
    __syncthreads();
    float acc = 0.f;
    for (int k = 0; k < HID; k++)
        acc += q[k] * W2l[k * HID + j] + p[k] * W2r[k * HID + j];
    pooled[j] = g_invng[g] * acc + b2[j];
    __syncthreads();
    float a2 = bf1[j];
    for (int k = 0; k < HID; k++)
        a2 += pooled[k] * Wf1[k * HID + j];
    for (int a = 0; a < 8; a++)
        a2 += gattr[g * 8 + a] * Wf1[(HID + a) * HID + j];
    float t1 = fmaxf(a2, 0.f);
    red[j] = t1 * Wf2[j];
    __syncthreads();
    for (int s = 128; s > 0; s >>= 1) {
        if (j < s) red[j] += red[j + s];
        __syncthreads();
    }
    if (j == 0) out[g] = red[0] + bf2[0];
}

// --------------------------- launch ---------------------------
extern "C" void kernel_launch(void* const* d_in, const int* in_sizes, int n_in,
                              void* d_out, int out_size) {
    const float* x = (const float*)d_in[0];
    const int* ei = (const int*)d_in[1];
    const int* batch = (const int*)d_in[2];
    const float* gattr = (const float*)d_in[3];
    const float* W1l = (const float*)d_in[4];
    const float* b1  = (const float*)d_in[5];
    const float* W1r = (const float*)d_in[6];
    const float* W2l = (const float*)d_in[7];
    const float* b2  = (const float*)d_in[8];
    const float* W2r = (const float*)d_in[9];
    const float* Wf1 = (const float*)d_in[10];
    const float* bf1 = (const float*)d_in[11];
    const float* Wf2 = (const float*)d_in[12];
    const float* bf2 = (const float*)d_in[13];
    float* out = (float*)d_out;

    init_k<<<2048, 256>>>(x, W1l, W1r);
    cnt_k<<<1563, 256>>>(ei, batch);
    scan1_k<<<NB1, 256>>>();
    scan2_k<<<1, 512>>>();
    scan3_k<<<NB1, 256>>>();
    placecoef_k<<<(NE + 255) / 256, 256>>>(ei, batch);   // 6th launch -> ncu sample
    agg1_k<<<(NN * 32 + 255) / 256, 256>>>();
    gemm1_k<<<(NN + 63) / 64, 256>>>(b1);
    gemm2_k<<<G2BLK, 256>>>();
    ppool_k<<<PBLK, 256>>>(batch);
    final_k<<<NG, 256>>>(gattr, W2l, b2, W2r, Wf1, bf1, Wf2, bf2, out);
}

// round 6
// speedup vs baseline: 3.2833x; 1.3670x over previous
#include <cuda_runtime.h>
#include <cuda_bf16.h>
#include <cstdint>

#define NN   100000
#define NE   1600000
#define NG   64
#define DIN  128
#define HID  256
#define NB1  391          // ceil(NN/256)
#define G1BLK 148
#define NTILE1 1563       // ceil(NN/64)
#define G2BLK 125         // gemm2 split-K blocks
#define G2CH  800         // 125*800 = 100000 exactly

// ------------- static device scratch (no allocations allowed) -------------
__device__ __align__(16) __nv_bfloat16 g_xb[(size_t)NN * DIN];     // 25.6 MB
__device__ __align__(16) __nv_bfloat16 g_agg1b[(size_t)NN * DIN];  // 25.6 MB
__device__ __align__(16) __nv_bfloat16 g_h1b[(size_t)NN * HID];    // 51.2 MB
__device__ __align__(16) __nv_bfloat16 g_Wcat[2 * DIN * HID];      // 128 KB
__device__ __align__(16) float g_coef[(size_t)NN * NG];            // 25.6 MB
__device__ __align__(16) float g_Qa[NG * HID];
__device__ __align__(16) float g_P[NG * HID];
__device__ __align__(16) int g_cnt[NN];
__device__ int   g_eoff[NN];
__device__ int   g_wpos[NN];
__device__ int   g_bsum[NB1];
__device__ int   g_boff[512];
__device__ int   g_ncnt[NG];
__device__ float g_invcnt[NN];
__device__ float g_invng[NG];
__device__ int   g_esrc[NE];

// --------------------------- helpers ---------------------------
__device__ __forceinline__ uint32_t pkbf(float lo, float hi) {
    __nv_bfloat162 h = __float22bfloat162_rn(make_float2(lo, hi));
    return *(uint32_t*)&h;
}
__device__ __forceinline__ uint32_t s2u(const void* p) {
    return (uint32_t)__cvta_generic_to_shared(p);
}
__device__ __forceinline__ void ldmA(uint32_t r[4], uint32_t addr) {
    asm volatile("ldmatrix.sync.aligned.m8n8.x4.shared.b16 {%0,%1,%2,%3}, [%4];"
                 : "=r"(r[0]), "=r"(r[1]), "=r"(r[2]), "=r"(r[3]) : "r"(addr));
}
__device__ __forceinline__ void ldmT(uint32_t r[4], uint32_t addr) {
    asm volatile("ldmatrix.sync.aligned.m8n8.x4.trans.shared.b16 {%0,%1,%2,%3}, [%4];"
                 : "=r"(r[0]), "=r"(r[1]), "=r"(r[2]), "=r"(r[3]) : "r"(addr));
}
__device__ __forceinline__ void mma16816(float c[4], const uint32_t a[4], const uint32_t b[2]) {
    asm volatile("mma.sync.aligned.m16n8k16.row.col.f32.bf16.bf16.f32 "
                 "{%0,%1,%2,%3}, {%4,%5,%6,%7}, {%8,%9}, {%0,%1,%2,%3};"
                 : "+f"(c[0]), "+f"(c[1]), "+f"(c[2]), "+f"(c[3])
                 : "r"(a[0]), "r"(a[1]), "r"(a[2]), "r"(a[3]), "r"(b[0]), "r"(b[1]));
}

// ---------------- init: zero scratch + convert x + build Wcat ----------------
__global__ void init_k(const float* __restrict__ x,
                       const float* __restrict__ W1l, const float* __restrict__ W1r) {
    size_t i = (size_t)blockIdx.x * blockDim.x + threadIdx.x;
    size_t stride = (size_t)gridDim.x * blockDim.x;
    float4 z = make_float4(0.f, 0.f, 0.f, 0.f);
    for (size_t j = i; j < (size_t)NN * NG / 4; j += stride)
        ((float4*)g_coef)[j] = z;
    for (size_t j = i; j < NN / 4; j += stride)
        ((int4*)g_cnt)[j] = make_int4(0, 0, 0, 0);
    for (size_t j = i; j < NG * HID / 4; j += stride) {
        ((float4*)g_Qa)[j] = z;
        ((float4*)g_P)[j] = z;
    }
    if (i < NG) g_ncnt[i] = 0;
    for (size_t j = i; j < (size_t)NN * DIN / 4; j += stride) {
        float4 v = ((const float4*)x)[j];
        ((uint2*)g_xb)[j] = make_uint2(pkbf(v.x, v.y), pkbf(v.z, v.w));
    }
    for (size_t j = i; j < (size_t)2 * DIN * HID / 4; j += stride) {
        size_t e = j * 4;
        int k = (int)(e >> 8), n = (int)(e & 255);
        const float* src = (k < DIN) ? &W1r[k * HID + n] : &W1l[(k - DIN) * HID + n];
        float4 v = *(const float4*)src;
        ((uint2*)g_Wcat)[j] = make_uint2(pkbf(v.x, v.y), pkbf(v.z, v.w));
    }
}

// ---------------- degree count + per-graph node count (fused, int4) ----------------
__global__ void cnt_k(const int* __restrict__ ei, const int* __restrict__ batch) {
    int i = blockIdx.x * blockDim.x + threadIdx.x;
    int stride = gridDim.x * blockDim.x;
    const int4* d4 = (const int4*)(ei + NE);
    for (int j = i; j < NE / 4; j += stride) {
        int4 d = d4[j];
        atomicAdd(&g_cnt[d.x], 1);
        atomicAdd(&g_cnt[d.y], 1);
        atomicAdd(&g_cnt[d.z], 1);
        atomicAdd(&g_cnt[d.w], 1);
    }
    const int4* b4 = (const int4*)batch;
    for (int j = i; j < NN / 4; j += stride) {
        int4 b = b4[j];
        if (b.x == b.w) {
            atomicAdd(&g_ncnt[b.x], 4);
        } else {
            atomicAdd(&g_ncnt[b.x], 1);
            atomicAdd(&g_ncnt[b.y], 1);
            atomicAdd(&g_ncnt[b.z], 1);
            atomicAdd(&g_ncnt[b.w], 1);
        }
    }
}

// --------------------------- exclusive scan of degrees ---------------------------
__global__ void scan1_k() {
    __shared__ int sh[256];
    int t = threadIdx.x;
    int i = blockIdx.x * 256 + t;
    int val = (i < NN) ? g_cnt[i] : 0;
    sh[t] = val;
    __syncthreads();
    for (int d = 1; d < 256; d <<= 1) {
        int add = (t >= d) ? sh[t - d] : 0;
        __syncthreads();
        sh[t] += add;
        __syncthreads();
    }
    if (i < NN) g_eoff[i] = sh[t] - val;
    if (t == 255) g_bsum[blockIdx.x] = sh[255];
}

__global__ void scan2_k() {
    __shared__ int sh[512];
    int t = threadIdx.x;
    int val = (t < NB1) ? g_bsum[t] : 0;
    sh[t] = val;
    __syncthreads();
    for (int d = 1; d < 512; d <<= 1) {
        int add = (t >= d) ? sh[t - d] : 0;
        __syncthreads();
        sh[t] += add;
        __syncthreads();
    }
    g_boff[t] = sh[t] - val;
}

__global__ void scan3_k() {
    int i = blockIdx.x * blockDim.x + threadIdx.x;
    if (i < NN) {
        int off = g_eoff[i] + g_boff[i >> 8];
        g_eoff[i] = off;
        g_wpos[i] = off;
        g_invcnt[i] = 1.0f / fmaxf((float)g_cnt[i], 1.0f);
    }
    if (i < NG) g_invng[i] = 1.0f / fmaxf((float)g_ncnt[i], 1.0f);
}

// ---------------- CSR placement + coef build (fused: one ei read) ----------------
__global__ void placecoef_k(const int* __restrict__ ei, const int* __restrict__ batch) {
    int e = blockIdx.x * blockDim.x + threadIdx.x;
    if (e < NE) {
        int s = ei[e];
        int d = ei[NE + e];
        int p = atomicAdd(&g_wpos[d], 1);
        g_esrc[p] = s;
        int g = batch[d];
        atomicAdd(&g_coef[(size_t)s * NG + g], g_invcnt[d]);
    }
}

// ---------------- layer-1 mean aggregation (warp/node, unroll-4 for MLP) ----------------
__global__ void agg1_k() {
    int gtid = blockIdx.x * blockDim.x + threadIdx.x;
    int v = gtid >> 5;
    if (v >= NN) return;
    int lane = gtid & 31;
    int start = g_eoff[v];
    int end = (v + 1 < NN) ? g_eoff[v + 1] : NE;
    float a0 = 0.f, a1 = 0.f, a2 = 0.f, a3 = 0.f;
    const uint2* xb2 = (const uint2*)g_xb;
    int i = start;
    for (; i + 4 <= end; i += 4) {
        int s0 = g_esrc[i], s1 = g_esrc[i + 1], s2 = g_esrc[i + 2], s3 = g_esrc[i + 3];
        uint2 t0 = xb2[(size_t)s0 * (DIN / 4) + lane];
        uint2 t1 = xb2[(size_t)s1 * (DIN / 4) + lane];
        uint2 t2 = xb2[(size_t)s2 * (DIN / 4) + lane];
        uint2 t3 = xb2[(size_t)s3 * (DIN / 4) + lane];
#define ACC(t)                                              \
        {                                                   \
            __nv_bfloat162 p0 = *(__nv_bfloat162*)&(t).x;   \
            __nv_bfloat162 p1 = *(__nv_bfloat162*)&(t).y;   \
            a0 += __bfloat162float(p0.x);                   \
            a1 += __bfloat162float(p0.y);                   \
            a2 += __bfloat162float(p1.x);                   \
            a3 += __bfloat162float(p1.y);                   \
        }
        ACC(t0) ACC(t1) ACC(t2) ACC(t3)
    }
    for (; i < end; ++i) {
        uint2 t = xb2[(size_t)g_esrc[i] * (DIN / 4) + lane];
        ACC(t)
    }
#undef ACC
    float w = g_invcnt[v];
    uint2 o = make_uint2(pkbf(a0 * w, a1 * w), pkbf(a2 * w, a3 * w));
    ((uint2*)g_agg1b)[(size_t)v * (DIN / 4) + lane] = o;
}

// ----------- GEMM1 (persistent, Wcat resident in smem): h1 = relu([x|agg1]@Wcat + b1) -----------
// 148 blocks, each loops over M-tiles of 64 rows. Dyn smem: Bs[256][264] + As[64][264].
__global__ void __launch_bounds__(256) gemm1_k(const float* __restrict__ b1) {
    extern __shared__ __nv_bfloat16 sm1[];
    __nv_bfloat16* Bs = sm1;                 // 256 x 264
    __nv_bfloat16* As = sm1 + 256 * 264;     // 64 x 264
    int tid = threadIdx.x;
    int wid = tid >> 5, lane = tid & 31;
    int mw = (wid & 1) * 32;
    int nw = (wid >> 1) * 64;

    // load full Wcat into padded smem (once)
    for (int j = tid; j < 256 * 32; j += 256) {
        int row = j >> 5, col = (j & 31) * 8;
        *(uint4*)&Bs[row * 264 + col] = *(const uint4*)&g_Wcat[(size_t)row * HID + col];
    }

    uint4 pa[8];
    int ti = blockIdx.x;

    // prefetch first A tile into registers
    if (ti < NTILE1) {
#pragma unroll
        for (int j = 0; j < 8; j++) {
            int idx = tid + j * 256;
            int row = idx >> 5, col = (idx & 31) * 8;
            int gr = ti * 64 + row;
            if (gr < NN) {
                const __nv_bfloat16* src = (col < DIN) ? &g_xb[(size_t)gr * DIN + col]
                                                       : &g_agg1b[(size_t)gr * DIN + (col - DIN)];
                pa[j] = *(const uint4*)src;
            } else pa[j] = make_uint4(0, 0, 0, 0);
        }
    }

    for (; ti < NTILE1; ti += G1BLK) {
        __syncthreads();   // previous tile's compute done (and Wcat load on iter 0)
#pragma unroll
        for (int j = 0; j < 8; j++) {
            int idx = tid + j * 256;
            int row = idx >> 5, col = (idx & 31) * 8;
            *(uint4*)&As[row * 264 + col] = pa[j];
        }
        __syncthreads();

        // prefetch next tile (overlaps compute)
        int tn = ti + G1BLK;
        if (tn < NTILE1) {
#pragma unroll
            for (int j = 0; j < 8; j++) {
                int idx = tid + j * 256;
                int row = idx >> 5, col = (idx & 31) * 8;
                int gr = tn * 64 + row;
                if (gr < NN) {
                    const __nv_bfloat16* src = (col < DIN) ? &g_xb[(size_t)gr * DIN + col]
                                                           : &g_agg1b[(size_t)gr * DIN + (col - DIN)];
                    pa[j] = *(const uint4*)src;
                } else pa[j] = make_uint4(0, 0, 0, 0);
            }
        }

        float acc[2][8][4];
#pragma unroll
        for (int i = 0; i < 2; i++)
#pragma unroll
            for (int j = 0; j < 8; j++)
#pragma unroll
                for (int q = 0; q < 4; q++) acc[i][j][q] = 0.f;

#pragma unroll
        for (int ks = 0; ks < 256; ks += 16) {
            uint32_t af[2][4];
#pragma unroll
            for (int mi = 0; mi < 2; mi++) {
                uint32_t addr = s2u(&As[(mw + mi * 16 + (lane & 15)) * 264 + ks + (lane >> 4) * 8]);
                ldmA(af[mi], addr);
            }
#pragma unroll
            for (int nf = 0; nf < 4; nf++) {
                uint32_t bf[4];
                uint32_t addr = s2u(&Bs[(ks + ((lane >> 3) & 1) * 8 + (lane & 7)) * 264 +
                                        nw + nf * 16 + (lane >> 4) * 8]);
                ldmT(bf, addr);
#pragma unroll
                for (int mi = 0; mi < 2; mi++) {
                    mma16816(acc[mi][nf * 2], af[mi], bf);
                    mma16816(acc[mi][nf * 2 + 1], af[mi], bf + 2);
                }
            }
        }

        int m0 = ti * 64;
        uint32_t* h1u = (uint32_t*)g_h1b;
#pragma unroll
        for (int mi = 0; mi < 2; mi++) {
#pragma unroll
            for (int nf = 0; nf < 8; nf++) {
                int col = nw + nf * 8 + (lane & 3) * 2;
                float bx = b1[col], by = b1[col + 1];
                int row = m0 + mw + mi * 16 + (lane >> 2);
                if (row < NN)
                    h1u[((size_t)row * HID + col) >> 1] =
                        pkbf(fmaxf(acc[mi][nf][0] + bx, 0.f), fmaxf(acc[mi][nf][1] + by, 0.f));
                int row2 = row + 8;
                if (row2 < NN)
                    h1u[((size_t)row2 * HID + col) >> 1] =
                        pkbf(fmaxf(acc[mi][nf][2] + bx, 0.f), fmaxf(acc[mi][nf][3] + by, 0.f));
            }
        }
    }
}

// ------- GEMM2 (bf16 mma) + fused pool: Qa = coef^T @ h1, P = segsum(h1) -------
__global__ void __launch_bounds__(256) gemm2_k(const int* __restrict__ batch) {
    __shared__ __align__(16) __nv_bfloat16 Ks[32 * 72];
    __shared__ __align__(16) __nv_bfloat16 Bs[32 * 264];
    __shared__ int sbatch[32];
    int tid = threadIdx.x;
    int wid = tid >> 5, lane = tid & 31;
    int nb = blockIdx.x * G2CH;
    int n0w = wid * 32;

    float acc[4][4][4];
#pragma unroll
    for (int i = 0; i < 4; i++)
#pragma unroll
        for (int j = 0; j < 4; j++)
#pragma unroll
            for (int q = 0; q < 4; q++) acc[i][j][q] = 0.f;

    int cnode = tid >> 3;
    int cg = (tid & 7) * 8;

    float4 cf0, cf1;
    uint4 hb[4];

    {
        size_t base = (size_t)(nb + cnode) * NG + cg;
        cf0 = *(const float4*)&g_coef[base];
        cf1 = *(const float4*)&g_coef[base + 4];
#pragma unroll
        for (int j = 0; j < 4; j++) {
            int c = tid + 256 * j;
            int row = c >> 5, col = (c & 31) * 8;
            hb[j] = *(const uint4*)&g_h1b[(size_t)(nb + row) * HID + col];
        }
    }

    int curg = batch[nb];
    float psum = 0.f;

    for (int s = 0; s < 25; s++) {
        __syncthreads();
        {
            uint4 kv = make_uint4(pkbf(cf0.x, cf0.y), pkbf(cf0.z, cf0.w),
                                  pkbf(cf1.x, cf1.y), pkbf(cf1.z, cf1.w));
            *(uint4*)&Ks[cnode * 72 + cg] = kv;
#pragma unroll
            for (int j = 0; j < 4; j++) {
                int c = tid + 256 * j;
                int row = c >> 5, col = (c & 31) * 8;
                *(uint4*)&Bs[row * 264 + col] = hb[j];
            }
            if (tid < 32) sbatch[tid] = batch[nb + s * 32 + tid];
        }
        __syncthreads();

        if (s + 1 < 25) {
            int kb = nb + (s + 1) * 32;
            size_t base = (size_t)(kb + cnode) * NG + cg;
            cf0 = *(const float4*)&g_coef[base];
            cf1 = *(const float4*)&g_coef[base + 4];
#pragma unroll
            for (int j = 0; j < 4; j++) {
                int c = tid + 256 * j;
                int row = c >> 5, col = (c & 31) * 8;
                hb[j] = *(const uint4*)&g_h1b[(size_t)(kb + row) * HID + col];
            }
        }

#pragma unroll
        for (int ks = 0; ks < 32; ks += 16) {
            uint32_t af[4][4];
#pragma unroll
            for (int mi = 0; mi < 4; mi++) {
                uint32_t addr = s2u(&Ks[(ks + ((lane >> 4) & 1) * 8 + (lane & 7)) * 72 +
                                        mi * 16 + ((lane >> 3) & 1) * 8]);
                ldmT(af[mi], addr);
            }
#pragma unroll
            for (int nf = 0; nf < 2; nf++) {
                uint32_t bf[4];
                uint32_t addr = s2u(&Bs[(ks + ((lane >> 3) & 1) * 8 + (lane & 7)) * 264 +
                                        n0w + nf * 16 + (lane >> 4) * 8]);
                ldmT(bf, addr);
#pragma unroll
                for (int mi = 0; mi < 4; mi++) {
                    mma16816(acc[mi][nf * 2], af[mi], bf);
                    mma16816(acc[mi][nf * 2 + 1], af[mi], bf + 2);
                }
            }
        }

        // fused pool: segmented column sum of this 32-row slab (graph id uniform per row)
        for (int r = 0; r < 32; r++) {
            int g = sbatch[r];
            float v = __bfloat162float(Bs[r * 264 + tid]);
            if (g != curg) {
                atomicAdd(&g_P[curg * HID + tid], psum);
                psum = 0.f;
                curg = g;
            }
            psum += v;
        }
    }
    atomicAdd(&g_P[curg * HID + tid], psum);

#pragma unroll
    for (int mi = 0; mi < 4; mi++) {
#pragma unroll
        for (int nf = 0; nf < 4; nf++) {
            int col = n0w + nf * 8 + (lane & 3) * 2;
            int row = mi * 16 + (lane >> 2);
            atomicAdd(&g_Qa[row * HID + col], acc[mi][nf][0]);
            atomicAdd(&g_Qa[row * HID + col + 1], acc[mi][nf][1]);
            atomicAdd(&g_Qa[(row + 8) * HID + col], acc[mi][nf][2]);
            atomicAdd(&g_Qa[(row + 8) * HID + col + 1], acc[mi][nf][3]);
        }
    }
}

// --------------------------- final: layer2 fold + pool + MLP head ---------------------------
__global__ void final_k(const float* __restrict__ gattr,
                        const float* __restrict__ W2l, const float* __restrict__ b2,
                        const float* __restrict__ W2r,
                        const float* __restrict__ Wf1, const float* __restrict__ bf1,
                        const float* __restrict__ Wf2, const float* __restrict__ bf2,
                        float* __restrict__ out) {
    __shared__ float q[HID], p[HID], pooled[HID], red[HID];
    int g = blockIdx.x, j = threadIdx.x;
    q[j] = g_Qa[g * HID + j];
    p[j] = g_P[g * HID + j];
    __syncthreads();
    float acc = 0.f;
    for (int k = 0; k < HID; k++)
        acc += q[k] * W2l[k * HID + j] + p[k] * W2r[k * HID + j];
    pooled[j] = g_invng[g] * acc + b2[j];
    __syncthreads();
    float a2 = bf1[j];
    for (int k = 0; k < HID; k++)
        a2 += pooled[k] * Wf1[k * HID + j];
    for (int a = 0; a < 8; a++)
        a2 += gattr[g * 8 + a] * Wf1[(HID + a) * HID + j];
    float t1 = fmaxf(a2, 0.f);
    red[j] = t1 * Wf2[j];
    __syncthreads();
    for (int s = 128; s > 0; s >>= 1) {
        if (j < s) red[j] += red[j + s];
        __syncthreads();
    }
    if (j == 0) out[g] = red[0] + bf2[0];
}

// --------------------------- launch ---------------------------
extern "C" void kernel_launch(void* const* d_in, const int* in_sizes, int n_in,
                              void* d_out, int out_size) {
    const float* x = (const float*)d_in[0];
    const int* ei = (const int*)d_in[1];
    const int* batch = (const int*)d_in[2];
    const float* gattr = (const float*)d_in[3];
    const float* W1l = (const float*)d_in[4];
    const float* b1  = (const float*)d_in[5];
    const float* W1r = (const float*)d_in[6];
    const float* W2l = (const float*)d_in[7];
    const float* b2  = (const float*)d_in[8];
    const float* W2r = (const float*)d_in[9];
    const float* Wf1 = (const float*)d_in[10];
    const float* bf1 = (const float*)d_in[11];
    const float* Wf2 = (const float*)d_in[12];
    const float* bf2 = (const float*)d_in[13];
    float* out = (float*)d_out;

    const int SMEM1 = (256 * 264 + 64 * 264) * (int)sizeof(__nv_bfloat16);  // 168960 B
    cudaFuncSetAttribute(gemm1_k, cudaFuncAttributeMaxDynamicSharedMemorySize, SMEM1);

    init_k<<<2048, 256>>>(x, W1l, W1r);
    cnt_k<<<1563, 256>>>(ei, batch);
    scan1_k<<<NB1, 256>>>();
    scan2_k<<<1, 512>>>();
    scan3_k<<<NB1, 256>>>();
    placecoef_k<<<(NE + 255) / 256, 256>>>(ei, batch);   // 6th launch -> ncu sample
    agg1_k<<<(NN * 32 + 255) / 256, 256>>>();
    gemm1_k<<<G1BLK, 256, SMEM1>>>(b1);
    gemm2_k<<<G2BLK, 256>>>(batch);
    final_k<<<NG, 256>>>(gattr, W2l, b2, W2r, Wf1, bf1, Wf2, bf2, out);
}